// round 6
// baseline (speedup 1.0000x reference)
#include <cuda_runtime.h>
#include <math.h>
#include <stdint.h>

// Problem constants
#define BATCH 32
#define SEQ   2048
#define PER   256      // PERIOD
#define NCH   256
#define KSEG  8        // SEQ/PER
#define LSEG  4        // PRED/PER
#define BN    (BATCH*NCH)   // 8192
#define EPSV  1e-5f

// ---------------- device scratch (no cudaMalloc allowed) ----------------
__device__ float g_pow[9][PER*PER];     // g_pow[m] = W^m, m=1..8 used
__device__ float g_v[12][PER];          // v_m = W^m @ ones, m=1..11
__device__ float g_rowsum[LSEG][PER];   // rowsum[l][q] = sum_k Wenc[l,k]*v_{K-k+l}[q]
__device__ float g_psum[8][BN];
__device__ float g_psumsq[8][BN];
__device__ float g_mean[BN];
__device__ float g_std[BN];
__device__ float g_z[LSEG][PER][BN];    // z_l[q][b*NCH+n] (l=1..3 used; slot 0 unused)

// ---------------- cp.async helpers ----------------
__device__ __forceinline__ uint32_t saddr(const void* p) {
    return (uint32_t)__cvta_generic_to_shared(p);
}
__device__ __forceinline__ void cp16(uint32_t s, const void* g) {
    asm volatile("cp.async.cg.shared.global [%0], [%1], 16;" :: "r"(s), "l"(g));
}
__device__ __forceinline__ void cp_commit() {
    asm volatile("cp.async.commit_group;");
}
__device__ __forceinline__ void cp_wait0() {
    asm volatile("cp.async.wait_group 0;");
}

// ---------------- packed f32x2 helpers (sm_103a) ----------------
// d = fma(a, b, d) per 32-bit lane; bit-identical to two scalar FFMA.rn.
__device__ __forceinline__ void ffma2(unsigned long long& d,
                                      unsigned long long a, unsigned long long b) {
    asm("fma.rn.f32x2 %0, %1, %2, %0;" : "+l"(d) : "l"(a), "l"(b));
}
__device__ __forceinline__ unsigned long long bcast2(float a) {
    unsigned long long r;
    asm("mov.b64 %0, {%1, %1};" : "=l"(r) : "f"(a));
    return r;
}
__device__ __forceinline__ void unpack2(unsigned long long v, float& lo, float& hi) {
    asm("mov.b64 {%0, %1}, %2;" : "=f"(lo), "=f"(hi) : "l"(v));
}

// ---------------- small kernels ----------------
__global__ void k_copyW(const float* __restrict__ Wb) {
    int i = blockIdx.x * 256 + threadIdx.x;
    if (i < PER * PER) g_pow[1][i] = Wb[i];
}

// Batched 256x256x256 fp32 matmul among g_pow slots: C[d]=A[a]*B[b], up to 4 per launch.
__global__ void __launch_bounds__(256) k_powmul(
    int d0,int a0,int b0,int d1,int a1,int b1,
    int d2,int a2,int b2,int d3,int a3,int b3)
{
    int pi = blockIdx.z;
    int d, a, b;
    if      (pi == 0) { d=d0; a=a0; b=b0; }
    else if (pi == 1) { d=d1; a=a1; b=b1; }
    else if (pi == 2) { d=d2; a=a2; b=b2; }
    else              { d=d3; a=a3; b=b3; }
    const float* __restrict__ A  = g_pow[a];
    const float* __restrict__ Bm = g_pow[b];
    float*       __restrict__ C  = g_pow[d];

    __shared__ float As[32][65];
    __shared__ float Bs[32][64];
    int tid = threadIdx.x;
    int ty = tid >> 4, tx = tid & 15;
    int row0 = blockIdx.y * 64, col0 = blockIdx.x * 64;
    float acc[16] = {};

    for (int pc = 0; pc < 256; pc += 32) {
        #pragma unroll
        for (int it = 0; it < 8; it++) {
            int e = tid + it * 256;
            int q = e >> 5, p = e & 31;
            As[p][q] = A[(row0 + q) * 256 + pc + p];
        }
        #pragma unroll
        for (int it = 0; it < 2; it++) {
            int e = tid + it * 256;
            int p = e >> 4, nv = e & 15;
            float4 v = *(const float4*)&Bm[(pc + p) * 256 + col0 + nv * 4];
            *(float4*)&Bs[p][nv * 4] = v;
        }
        __syncthreads();
        #pragma unroll
        for (int pk = 0; pk < 32; pk++) {
            float av[4];
            #pragma unroll
            for (int i = 0; i < 4; i++) av[i] = As[pk][ty * 4 + i];
            float4 b4 = *(const float4*)&Bs[pk][tx * 4];
            float bv[4] = {b4.x, b4.y, b4.z, b4.w};
            #pragma unroll
            for (int i = 0; i < 4; i++)
                #pragma unroll
                for (int j = 0; j < 4; j++)
                    acc[i * 4 + j] += av[i] * bv[j];
        }
        __syncthreads();
    }
    #pragma unroll
    for (int i = 0; i < 4; i++) {
        float4 o = make_float4(acc[i*4], acc[i*4+1], acc[i*4+2], acc[i*4+3]);
        *(float4*)&C[(row0 + ty * 4 + i) * 256 + col0 + tx * 4] = o;
    }
}

// v_m = rowsum(W^m) for m=1..8 (one warp per output row)
__global__ void k_v_rowsums() {
    int m = blockIdx.y + 1;                       // 1..8
    int warp = threadIdx.x >> 5, lane = threadIdx.x & 31;
    int q = blockIdx.x * 8 + warp;                // 32 blocks * 8 warps = 256 rows
    const float* __restrict__ A = g_pow[m];
    float s = 0.f;
    #pragma unroll
    for (int i = 0; i < 8; i++) s += A[q * 256 + lane + i * 32];
    #pragma unroll
    for (int o = 16; o > 0; o >>= 1) s += __shfl_xor_sync(0xffffffffu, s, o);
    if (lane == 0) g_v[m][q] = s;
}

// v_{8+i} = W^8 @ v_i for i=1..3
__global__ void k_v_ext() {
    __shared__ float vs[PER];
    int i = blockIdx.y + 1;                       // 1..3
    int warp = threadIdx.x >> 5, lane = threadIdx.x & 31;
    int q = blockIdx.x * 8 + warp;
    if (threadIdx.x < PER) vs[threadIdx.x] = g_v[i][threadIdx.x];
    __syncthreads();
    const float* __restrict__ A = g_pow[8];
    float s = 0.f;
    #pragma unroll
    for (int c = 0; c < 8; c++) {
        int p = lane + c * 32;
        s += A[q * 256 + p] * vs[p];
    }
    #pragma unroll
    for (int o = 16; o > 0; o >>= 1) s += __shfl_xor_sync(0xffffffffu, s, o);
    if (lane == 0) g_v[8 + i][q] = s;
}

__global__ void k_rowsum(const float* __restrict__ Wenc) {
    int t = blockIdx.x * 256 + threadIdx.x;       // 0..1023
    int l = t >> 8, q = t & 255;
    float s = 0.f;
    #pragma unroll
    for (int k = 0; k < KSEG; k++)
        s += __ldg(&Wenc[l * KSEG + k]) * g_v[KSEG - k + l][q];
    g_rowsum[l][q] = s;
}

// ---------------- stats ----------------
__global__ void k_stats1(const float* __restrict__ x) {
    int b = blockIdx.x, tc = blockIdx.y, n = threadIdx.x;
    const float* p = x + ((size_t)b * SEQ + (size_t)tc * 256) * NCH + n;
    float s = 0.f, s2 = 0.f;
    #pragma unroll 8
    for (int t = 0; t < 256; t++) {
        float v = __ldg(&p[(size_t)t * NCH]);
        s += v; s2 += v * v;
    }
    g_psum[tc][b * NCH + n] = s;
    g_psumsq[tc][b * NCH + n] = s2;
}

__global__ void k_stats2() {
    int bn = blockIdx.x * 256 + threadIdx.x;
    float s = 0.f, s2 = 0.f;
    #pragma unroll
    for (int i = 0; i < 8; i++) { s += g_psum[i][bn]; s2 += g_psumsq[i][bn]; }
    float m = s * (1.f / SEQ);
    float var = s2 * (1.f / SEQ) - m * m;
    g_mean[bn] = m;
    g_std[bn]  = sqrtf(var + EPSV);
}

// ---------------- GEMM 1: z_l = sum_k Wenc[l,k] * (W^(8-k) @ seg_k), raw x ----------------
// l=0 output is fused here (W^0 = I): out_0 = z_0 + mean*(1-rowsum0) + b0*std.
// Double-buffered: cp.async for B (x) tiles, register-prefetch for A (W^m) tiles.
// Inner product uses packed fma.rn.f32x2 (2 fp32 FMA per instruction).
__global__ void __launch_bounds__(256, 2) k_gemm_z(const float* __restrict__ x,
                                                    const float* __restrict__ Wenc,
                                                    float* __restrict__ out,
                                                    const float* __restrict__ benc) {
    __shared__ float As[2][32][65];
    __shared__ float Bs[2][32][64];
    int tid = threadIdx.x;
    int ty = tid >> 4, tx = tid & 15;
    int q0 = blockIdx.x * 64;                 // q tile (4 tiles)
    int bnt = blockIdx.y;                     // 0..127
    int b = bnt >> 2, n0 = (bnt & 3) * 64;
    const float* __restrict__ xb = x + (size_t)b * SEQ * NCH;

    unsigned long long accp[LSEG][8] = {};    // packed f32x2 accumulators
    unsigned long long yp[8] = {};
    float ra[8];
    float rnext[8];

    const int NIT = KSEG * (PER / 32);        // 64 chunks

    // prologue: load chunk 0
    {
        const float* __restrict__ A = g_pow[KSEG];   // k=0
        #pragma unroll
        for (int i = 0; i < 8; i++) {
            int e = tid + i * 256;
            int q = e >> 5, p = e & 31;
            ra[i] = __ldg(&A[(q0 + q) * PER + p]);
        }
        #pragma unroll
        for (int i = 0; i < 2; i++) {
            int e = tid + i * 256;
            int p = e >> 4, nv = e & 15;
            cp16(saddr(&Bs[0][p][nv * 4]), &xb[(size_t)p * NCH + n0 + nv * 4]);
        }
        cp_commit();
    }

    for (int it = 0; it < NIT; it++) {
        int buf = it & 1;

        // A prefetch for it+1 into regs (no smem hazard)
        if (it + 1 < NIT) {
            int nk = (it + 1) >> 3, npc = ((it + 1) & 7) << 5;
            const float* __restrict__ A = g_pow[KSEG - nk];
            #pragma unroll
            for (int i = 0; i < 8; i++) {
                int e = tid + i * 256;
                int q = e >> 5, p = e & 31;
                rnext[i] = __ldg(&A[(q0 + q) * PER + npc + p]);
            }
        }

        cp_wait0();                                   // B(it) landed (this thread's copies)
        #pragma unroll
        for (int i = 0; i < 8; i++) {                 // stage A(it) regs -> smem
            int e = tid + i * 256;
            int q = e >> 5, p = e & 31;
            As[buf][p][q] = ra[i];
        }
        __syncthreads();                              // tiles (it) visible; (it-1) compute done

        if (it + 1 < NIT) {                           // B prefetch for it+1 into buf^1
            int nk = (it + 1) >> 3, npc = ((it + 1) & 7) << 5;
            #pragma unroll
            for (int i = 0; i < 2; i++) {
                int e = tid + i * 256;
                int p = e >> 4, nv = e & 15;
                cp16(saddr(&Bs[buf ^ 1][p][nv * 4]),
                     &xb[(size_t)(nk * PER + npc + p) * NCH + n0 + nv * 4]);
            }
            cp_commit();
            #pragma unroll
            for (int i = 0; i < 8; i++) ra[i] = rnext[i];
        }

        // compute chunk it (packed f32x2)
        #pragma unroll
        for (int pk = 0; pk < 32; pk++) {
            ulonglong2 bb = *(const ulonglong2*)&Bs[buf][pk][tx * 4];
            #pragma unroll
            for (int i = 0; i < 4; i++) {
                unsigned long long aa = bcast2(As[buf][pk][ty * 4 + i]);
                ffma2(yp[i * 2],     aa, bb.x);
                ffma2(yp[i * 2 + 1], aa, bb.y);
            }
        }

        if ((it & 7) == 7) {                          // end of segment k: combine into acc
            int k = it >> 3;
            #pragma unroll
            for (int l = 0; l < LSEG; l++) {
                unsigned long long wl2 = bcast2(__ldg(&Wenc[l * KSEG + k]));
                #pragma unroll
                for (int t = 0; t < 8; t++) ffma2(accp[l][t], wl2, yp[t]);
            }
            #pragma unroll
            for (int t = 0; t < 8; t++) yp[t] = 0ull;
        }
    }

    // l = 1..3: stash z for the second GEMM
    #pragma unroll
    for (int l = 1; l < LSEG; l++)
        #pragma unroll
        for (int i = 0; i < 4; i++) {
            float o0, o1, o2, o3;
            unpack2(accp[l][i * 2],     o0, o1);
            unpack2(accp[l][i * 2 + 1], o2, o3);
            float4 o = make_float4(o0, o1, o2, o3);
            *(float4*)&g_z[l][q0 + ty * 4 + i][(size_t)b * NCH + n0 + tx * 4] = o;
        }

    // l = 0: final output directly (W^0 = I)
    {
        float be = __ldg(&benc[0]);
        #pragma unroll
        for (int i = 0; i < 4; i++) {
            int qq = q0 + ty * 4 + i;
            float rs = g_rowsum[0][qq];
            float a0, a1, a2, a3;
            unpack2(accp[0][i * 2],     a0, a1);
            unpack2(accp[0][i * 2 + 1], a2, a3);
            float av[4] = {a0, a1, a2, a3};
            float4 o;
            float* op = (float*)&o;
            #pragma unroll
            for (int j = 0; j < 4; j++) {
                int n  = n0 + tx * 4 + j;
                int bn = b * NCH + n;
                op[j] = av[j] + g_mean[bn] * (1.f - rs) + be * g_std[bn];
            }
            *(float4*)&out[(size_t)b * (LSEG * PER * NCH) + (size_t)qq * NCH + n0 + tx * 4] = o;
        }
    }
}

// ---------------- GEMM 2 + epilogue: out_l = W^l @ z_l  (l = 1..3) ----------------
__global__ void __launch_bounds__(256, 2) k_gemm_out(float* __restrict__ out,
                                                      const float* __restrict__ benc) {
    __shared__ float As[2][32][65];
    __shared__ float Bs[2][32][64];
    int l = blockIdx.z + 1;                   // 1..3
    const float* __restrict__ A  = g_pow[l];
    const float* __restrict__ Bm = &g_z[l][0][0];
    int tid = threadIdx.x;
    int ty = tid >> 4, tx = tid & 15;
    int q0 = blockIdx.x * 64;
    int bnt = blockIdx.y;
    int b = bnt >> 2, n0 = (bnt & 3) * 64;

    unsigned long long accp[8] = {};
    float ra[8];
    float rnext[8];
    const int NIT = PER / 32;                 // 8 chunks

    {
        #pragma unroll
        for (int i = 0; i < 8; i++) {
            int e = tid + i * 256;
            int q = e >> 5, p = e & 31;
            ra[i] = __ldg(&A[(q0 + q) * PER + p]);
        }
        #pragma unroll
        for (int i = 0; i < 2; i++) {
            int e = tid + i * 256;
            int p = e >> 4, nv = e & 15;
            cp16(saddr(&Bs[0][p][nv * 4]), &Bm[(size_t)p * BN + b * NCH + n0 + nv * 4]);
        }
        cp_commit();
    }

    for (int it = 0; it < NIT; it++) {
        int buf = it & 1;

        if (it + 1 < NIT) {
            int npc = (it + 1) << 5;
            #pragma unroll
            for (int i = 0; i < 8; i++) {
                int e = tid + i * 256;
                int q = e >> 5, p = e & 31;
                rnext[i] = __ldg(&A[(q0 + q) * PER + npc + p]);
            }
        }

        cp_wait0();
        #pragma unroll
        for (int i = 0; i < 8; i++) {
            int e = tid + i * 256;
            int q = e >> 5, p = e & 31;
            As[buf][p][q] = ra[i];
        }
        __syncthreads();

        if (it + 1 < NIT) {
            int npc = (it + 1) << 5;
            #pragma unroll
            for (int i = 0; i < 2; i++) {
                int e = tid + i * 256;
                int p = e >> 4, nv = e & 15;
                cp16(saddr(&Bs[buf ^ 1][p][nv * 4]),
                     &Bm[(size_t)(npc + p) * BN + b * NCH + n0 + nv * 4]);
            }
            cp_commit();
            #pragma unroll
            for (int i = 0; i < 8; i++) ra[i] = rnext[i];
        }

        #pragma unroll
        for (int pk = 0; pk < 32; pk++) {
            ulonglong2 bb = *(const ulonglong2*)&Bs[buf][pk][tx * 4];
            #pragma unroll
            for (int i = 0; i < 4; i++) {
                unsigned long long aa = bcast2(As[buf][pk][ty * 4 + i]);
                ffma2(accp[i * 2],     aa, bb.x);
                ffma2(accp[i * 2 + 1], aa, bb.y);
            }
        }
    }

    float be = __ldg(&benc[l]);
    #pragma unroll
    for (int i = 0; i < 4; i++) {
        int qq = q0 + ty * 4 + i;
        float rs = g_rowsum[l][qq];
        float a0, a1, a2, a3;
        unpack2(accp[i * 2],     a0, a1);
        unpack2(accp[i * 2 + 1], a2, a3);
        float av[4] = {a0, a1, a2, a3};
        float4 o;
        float* op = (float*)&o;
        #pragma unroll
        for (int j = 0; j < 4; j++) {
            int n  = n0 + tx * 4 + j;
            int bn = b * NCH + n;
            op[j] = av[j] + g_mean[bn] * (1.f - rs) + be * g_std[bn];
        }
        *(float4*)&out[(size_t)b * (LSEG * PER * NCH) + (size_t)(l * PER + qq) * NCH + n0 + tx * 4] = o;
    }
}

// ---------------- launcher ----------------
extern "C" void kernel_launch(void* const* d_in, const int* in_sizes, int n_in,
                              void* d_out, int out_size) {
    const float *x = nullptr, *Wb = nullptr, *We = nullptr, *be = nullptr;
    for (int i = 0; i < n_in; i++) {
        if      (in_sizes[i] == BATCH * SEQ * NCH) x  = (const float*)d_in[i];
        else if (in_sizes[i] == PER * PER)         Wb = (const float*)d_in[i];
        else if (in_sizes[i] == LSEG * KSEG)       We = (const float*)d_in[i];
        else if (in_sizes[i] == LSEG)              be = (const float*)d_in[i];
    }
    float* out = (float*)d_out;

    // DRAM-heavy stats first (keeps HBM busy while the small serial chain runs next)
    k_stats1<<<dim3(32,8), 256>>>(x);
    k_stats2<<<32, 256>>>();

    // W^1 .. W^8 via log-depth chain
    k_copyW<<<256, 256>>>(Wb);
    k_powmul<<<dim3(4,4,1), 256>>>(2,1,1,  0,0,0, 0,0,0, 0,0,0);
    k_powmul<<<dim3(4,4,2), 256>>>(3,2,1,  4,2,2, 0,0,0, 0,0,0);
    k_powmul<<<dim3(4,4,4), 256>>>(5,4,1,  6,4,2, 7,4,3, 8,4,4);

    // rowsum vectors v_m = W^m @ 1, m=1..11, then per-(l,q) rowsums
    k_v_rowsums<<<dim3(32,8), 256>>>();
    k_v_ext    <<<dim3(32,3), 256>>>();
    k_rowsum   <<<4, 256>>>(We);

    // heavy GEMMs + epilogues (l=0 output fused into k_gemm_z)
    k_gemm_z  <<<dim3(4,128),   256>>>(x, We, out, be);
    k_gemm_out<<<dim3(4,128,3), 256>>>(out, be);
}

// round 12
// speedup vs baseline: 1.4512x; 1.4512x over previous
#include <cuda_runtime.h>
#include <cuda_bf16.h>
#include <math.h>
#include <stdint.h>

// Problem constants
#define BATCH 32
#define SEQ   2048
#define PER   256
#define NCH   256
#define KSEG  8
#define LSEG  4
#define BN    (BATCH*NCH)   // 8192
#define EPSV  1e-5f

// ---------------- device scratch ----------------
__device__ float g_pow[9][PER*PER];          // W^m fp32, m=1..8
__device__ unsigned short g_powh[9][PER*PER]; // bf16 hi (exact truncation)
__device__ unsigned short g_powl[9][PER*PER]; // bf16 lo (residual)
__device__ float g_v[12][PER];
__device__ float g_rowsum[LSEG][PER];
__device__ float g_psum[8][BN];
__device__ float g_psumsq[8][BN];
__device__ float g_mean[BN];
__device__ float g_std[BN];
__device__ float g_z[LSEG][PER][BN];         // fp32

// ---------------- helpers ----------------
__device__ __forceinline__ uint32_t saddr(const void* p) {
    return (uint32_t)__cvta_generic_to_shared(p);
}
__device__ __forceinline__ void cp16(uint32_t s, const void* g) {
    asm volatile("cp.async.cg.shared.global [%0], [%1], 16;" :: "r"(s), "l"(g));
}
__device__ __forceinline__ void cp_commit() { asm volatile("cp.async.commit_group;"); }
__device__ __forceinline__ void cp_wait0()  { asm volatile("cp.async.wait_group 0;"); }

// mma.sync m16n8k16 bf16 -> f32, C += A*B
__device__ __forceinline__ void mma16816(float* c, const unsigned* a, unsigned b0, unsigned b1) {
    asm volatile(
        "mma.sync.aligned.m16n8k16.row.col.f32.bf16.bf16.f32 "
        "{%0,%1,%2,%3}, {%4,%5,%6,%7}, {%8,%9}, {%0,%1,%2,%3};"
        : "+f"(c[0]), "+f"(c[1]), "+f"(c[2]), "+f"(c[3])
        : "r"(a[0]), "r"(a[1]), "r"(a[2]), "r"(a[3]), "r"(b0), "r"(b1));
}

__device__ __forceinline__ void split_bf16(float v, unsigned short& h, unsigned short& l) {
    unsigned bits = __float_as_uint(v);
    unsigned hb = bits & 0xFFFF0000u;
    h = (unsigned short)(hb >> 16);
    float lf = v - __uint_as_float(hb);
    l = __bfloat16_as_ushort(__float2bfloat16(lf));
}

// ---------------- W-power kernel (fp32, 32x64 tiles, 4 products/launch) ----
__global__ void __launch_bounds__(256) k_pm(const float* __restrict__ Wb,
                                            int4 c0, int4 c1, int4 c2, int4 c3)
{
    int4 c = (blockIdx.z == 0) ? c0 : (blockIdx.z == 1) ? c1
           : (blockIdx.z == 2) ? c2 : c3;
    int tid = threadIdx.x;

    if (c.w == 1) {                       // copy mode
        int blk = blockIdx.y * 4 + blockIdx.x;
        int base = blk * 2048 + tid * 8;
        float4 v0 = *(const float4*)&Wb[base];
        float4 v1 = *(const float4*)&Wb[base + 4];
        *(float4*)&g_pow[c.x][base]     = v0;
        *(float4*)&g_pow[c.x][base + 4] = v1;
        return;
    }

    const float* __restrict__ A  = (c.y == 0) ? Wb : g_pow[c.y];
    const float* __restrict__ Bm = (c.z == 0) ? Wb : g_pow[c.z];
    float*       __restrict__ C  = g_pow[c.x];

    __shared__ float As[32][33];
    __shared__ float Bs[32][64];
    int ty = tid >> 4, tx = tid & 15;
    int row0 = blockIdx.y * 32, col0 = blockIdx.x * 64;
    float acc[8] = {};

    for (int pc = 0; pc < 256; pc += 32) {
        #pragma unroll
        for (int it = 0; it < 4; it++) {
            int e = tid + it * 256;
            int q = e >> 5, p = e & 31;
            As[p][q] = A[(row0 + q) * 256 + pc + p];
        }
        #pragma unroll
        for (int it = 0; it < 2; it++) {
            int e = tid + it * 256;
            int p = e >> 4, nv = e & 15;
            float4 v = *(const float4*)&Bm[(pc + p) * 256 + col0 + nv * 4];
            *(float4*)&Bs[p][nv * 4] = v;
        }
        __syncthreads();
        #pragma unroll
        for (int pk = 0; pk < 32; pk++) {
            float a0 = As[pk][ty * 2], a1 = As[pk][ty * 2 + 1];
            float4 b4 = *(const float4*)&Bs[pk][tx * 4];
            acc[0] += a0 * b4.x; acc[1] += a0 * b4.y;
            acc[2] += a0 * b4.z; acc[3] += a0 * b4.w;
            acc[4] += a1 * b4.x; acc[5] += a1 * b4.y;
            acc[6] += a1 * b4.z; acc[7] += a1 * b4.w;
        }
        __syncthreads();
    }
    *(float4*)&C[(row0 + ty * 2)     * 256 + col0 + tx * 4] =
        make_float4(acc[0], acc[1], acc[2], acc[3]);
    *(float4*)&C[(row0 + ty * 2 + 1) * 256 + col0 + tx * 4] =
        make_float4(acc[4], acc[5], acc[6], acc[7]);
}

// ---------------- convert W powers to bf16 hi/lo ----------------
__global__ void k_powcvt() {
    int m = blockIdx.y + 1;                     // 1..8
    int i = blockIdx.x * 256 + threadIdx.x;     // 0..65535
    float v = g_pow[m][i];
    unsigned short h, l;
    split_bf16(v, h, l);
    g_powh[m][i] = h;
    g_powl[m][i] = l;
}

// ---------------- small kernels ----------------
__global__ void k_v_rowsums() {
    int m = blockIdx.y + 1;
    int warp = threadIdx.x >> 5, lane = threadIdx.x & 31;
    int q = blockIdx.x * 8 + warp;
    const float* __restrict__ A = g_pow[m];
    float s = 0.f;
    #pragma unroll
    for (int i = 0; i < 8; i++) s += A[q * 256 + lane + i * 32];
    #pragma unroll
    for (int o = 16; o > 0; o >>= 1) s += __shfl_xor_sync(0xffffffffu, s, o);
    if (lane == 0) g_v[m][q] = s;
}

__global__ void k_v_ext() {
    __shared__ float vs[PER];
    int i = blockIdx.y + 1;
    int warp = threadIdx.x >> 5, lane = threadIdx.x & 31;
    int q = blockIdx.x * 8 + warp;
    if (threadIdx.x < PER) vs[threadIdx.x] = g_v[i][threadIdx.x];
    __syncthreads();
    const float* __restrict__ A = g_pow[8];
    float s = 0.f;
    #pragma unroll
    for (int c = 0; c < 8; c++) {
        int p = lane + c * 32;
        s += A[q * 256 + p] * vs[p];
    }
    #pragma unroll
    for (int o = 16; o > 0; o >>= 1) s += __shfl_xor_sync(0xffffffffu, s, o);
    if (lane == 0) g_v[8 + i][q] = s;
}

__global__ void k_rowsum(const float* __restrict__ Wenc) {
    int t = blockIdx.x * 256 + threadIdx.x;
    int l = t >> 8, q = t & 255;
    float s = 0.f;
    #pragma unroll
    for (int k = 0; k < KSEG; k++)
        s += __ldg(&Wenc[l * KSEG + k]) * g_v[KSEG - k + l][q];
    g_rowsum[l][q] = s;
}

__global__ void k_stats1(const float* __restrict__ x) {
    int b = blockIdx.x, tc = blockIdx.y, n = threadIdx.x;
    const float* p = x + ((size_t)b * SEQ + (size_t)tc * 256) * NCH + n;
    float s = 0.f, s2 = 0.f;
    #pragma unroll 8
    for (int t = 0; t < 256; t++) {
        float v = __ldg(&p[(size_t)t * NCH]);
        s += v; s2 += v * v;
    }
    g_psum[tc][b * NCH + n] = s;
    g_psumsq[tc][b * NCH + n] = s2;
}

__global__ void k_stats2() {
    int bn = blockIdx.x * 256 + threadIdx.x;
    float s = 0.f, s2 = 0.f;
    #pragma unroll
    for (int i = 0; i < 8; i++) { s += g_psum[i][bn]; s2 += g_psumsq[i][bn]; }
    float m = s * (1.f / SEQ);
    float var = s2 * (1.f / SEQ) - m * m;
    g_mean[bn] = m;
    g_std[bn]  = sqrtf(var + EPSV);
}

// ---------------- GEMM 1 (tensor): z_l = sum_k Wenc[l,k] * (W^(8-k) @ seg_k) ----
// CTA: 64(q) x 64(n); 8 warps of 16x32. bf16 hi/lo split, 3 products per mma tile.
// A (W powers, pre-split bf16 in gmem) via cp.async; B (x fp32) LDG->split->STS.
#define AR 40   // A smem row stride in bf16 elems (32 + 8 pad -> 80B, 16B aligned)
#define BR 34   // B smem row stride in bf16 elems (32 + 2 pad -> 68B)
__global__ void __launch_bounds__(256, 2) k_gemm_z(const float* __restrict__ x,
                                                    const float* __restrict__ Wenc) {
    __shared__ unsigned short AhS[2][64 * AR], AlS[2][64 * AR];
    __shared__ unsigned short BhS[2][64 * BR], BlS[2][64 * BR];

    int tid = threadIdx.x;
    int lane = tid & 31, warp = tid >> 5;
    int wrow = (warp & 3) * 16;          // q offset of warp tile
    int wcol = (warp >> 2) * 32;         // n offset of warp tile
    int grp = lane >> 2;                 // 0..7
    int tig = lane & 3;                  // threadID_in_group
    int kp  = tig * 2;

    int q0 = blockIdx.x * 64;
    int bnt = blockIdx.y;
    int b = bnt >> 2, n0 = (bnt & 3) * 64;
    const float* __restrict__ xb = x + (size_t)b * SEQ * NCH;

    // staging indices
    int arow = tid >> 2, aseg = tid & 3;         // A cp.async: 64 rows x 4 segs
    int bk = tid >> 3, bnq = tid & 7;            // B: k row 0..31, n-quad 0..7

    float y[4][4] = {};        // mma accumulators (4 n-tiles)
    float accl[LSEG][16] = {}; // per-l merged accumulators
    float rb[8];

    const int NIT = 64;        // 2048 K / 32 chunk

    // prologue: A(0) via cp.async, B(0) LDG
    {
        const unsigned short* Ah = g_powh[KSEG];
        const unsigned short* Al = g_powl[KSEG];
        size_t off = (size_t)(q0 + arow) * 256 + aseg * 8;
        cp16(saddr(&AhS[0][arow * AR + aseg * 8]), Ah + off);
        cp16(saddr(&AlS[0][arow * AR + aseg * 8]), Al + off);
        cp_commit();
        float4 r0 = *(const float4*)&xb[(size_t)bk * NCH + n0 + bnq * 8];
        float4 r1 = *(const float4*)&xb[(size_t)bk * NCH + n0 + bnq * 8 + 4];
        rb[0]=r0.x; rb[1]=r0.y; rb[2]=r0.z; rb[3]=r0.w;
        rb[4]=r1.x; rb[5]=r1.y; rb[6]=r1.z; rb[7]=r1.w;
    }

    for (int it = 0; it < NIT; it++) {
        int buf = it & 1;

        cp_wait0();                               // A(it) landed
        // stage B(it): split fp32 -> bf16 hi/lo, transpose to [n][k]
        #pragma unroll
        for (int j = 0; j < 8; j++) {
            unsigned short h, l;
            split_bf16(rb[j], h, l);
            int idx = (bnq * 8 + j) * BR + bk;
            BhS[buf][idx] = h;
            BlS[buf][idx] = l;
        }
        __syncthreads();                          // A(it)+B(it) visible; compute(it-1) done

        if (it + 1 < NIT) {                       // A(it+1) cp.async into buf^1
            int c = it + 1;
            int m = KSEG - (c >> 3), kc = (c & 7) * 32;
            size_t off = (size_t)(q0 + arow) * 256 + kc + aseg * 8;
            cp16(saddr(&AhS[buf ^ 1][arow * AR + aseg * 8]), &g_powh[m][off]);
            cp16(saddr(&AlS[buf ^ 1][arow * AR + aseg * 8]), &g_powl[m][off]);
            cp_commit();
            // B(it+1) LDG (latency hidden by compute below)
            float4 r0 = *(const float4*)&xb[(size_t)(c * 32 + bk) * NCH + n0 + bnq * 8];
            float4 r1 = *(const float4*)&xb[(size_t)(c * 32 + bk) * NCH + n0 + bnq * 8 + 4];
            rb[0]=r0.x; rb[1]=r0.y; rb[2]=r0.z; rb[3]=r0.w;
            rb[4]=r1.x; rb[5]=r1.y; rb[6]=r1.z; rb[7]=r1.w;
        }

        // compute chunk it: 2 k16 steps
        #pragma unroll
        for (int s = 0; s < 2; s++) {
            int ko = s * 16;
            unsigned ah[4], al[4];
            int r0i = (wrow + grp) * AR + ko + kp;
            int r1i = (wrow + grp + 8) * AR + ko + kp;
            ah[0] = *(const unsigned*)&AhS[buf][r0i];
            ah[1] = *(const unsigned*)&AhS[buf][r1i];
            ah[2] = *(const unsigned*)&AhS[buf][r0i + 8];
            ah[3] = *(const unsigned*)&AhS[buf][r1i + 8];
            al[0] = *(const unsigned*)&AlS[buf][r0i];
            al[1] = *(const unsigned*)&AlS[buf][r1i];
            al[2] = *(const unsigned*)&AlS[buf][r0i + 8];
            al[3] = *(const unsigned*)&AlS[buf][r1i + 8];
            #pragma unroll
            for (int nt = 0; nt < 4; nt++) {
                int ci = (wcol + nt * 8 + grp) * BR + ko + kp;
                unsigned bh0 = *(const unsigned*)&BhS[buf][ci];
                unsigned bh1 = *(const unsigned*)&BhS[buf][ci + 8];
                unsigned bl0 = *(const unsigned*)&BlS[buf][ci];
                unsigned bl1 = *(const unsigned*)&BlS[buf][ci + 8];
                mma16816(y[nt], ah, bh0, bh1);
                mma16816(y[nt], ah, bl0, bl1);
                mma16816(y[nt], al, bh0, bh1);
            }
        }

        if ((it & 7) == 7) {                      // segment boundary: merge
            int k = it >> 3;
            #pragma unroll
            for (int l = 0; l < LSEG; l++) {
                float wl = __ldg(&Wenc[l * KSEG + k]);
                #pragma unroll
                for (int nt = 0; nt < 4; nt++)
                    #pragma unroll
                    for (int r = 0; r < 4; r++)
                        accl[l][nt * 4 + r] += wl * y[nt][r];
            }
            #pragma unroll
            for (int nt = 0; nt < 4; nt++)
                #pragma unroll
                for (int r = 0; r < 4; r++) y[nt][r] = 0.f;
        }
    }

    // epilogue: write z_l for all l (fragment layout: c0,c1 row grp; c2,c3 row grp+8)
    int rowq = q0 + wrow + grp;
    #pragma unroll
    for (int l = 0; l < LSEG; l++)
        #pragma unroll
        for (int nt = 0; nt < 4; nt++) {
            int nn = n0 + wcol + nt * 8 + kp;
            *(float2*)&g_z[l][rowq][(size_t)b * NCH + nn] =
                make_float2(accl[l][nt * 4 + 0], accl[l][nt * 4 + 1]);
            *(float2*)&g_z[l][rowq + 8][(size_t)b * NCH + nn] =
                make_float2(accl[l][nt * 4 + 2], accl[l][nt * 4 + 3]);
        }
}

// ---------------- GEMM 2 (tensor) + epilogue: out_l = W^l @ z_l, l=1..3 ----------
__global__ void __launch_bounds__(256, 2) k_gemm_out(float* __restrict__ out,
                                                      const float* __restrict__ benc) {
    __shared__ unsigned short AhS[2][64 * AR], AlS[2][64 * AR];
    __shared__ unsigned short BhS[2][64 * BR], BlS[2][64 * BR];

    int l = blockIdx.z + 1;
    const float* __restrict__ Bm = &g_z[l][0][0];
    int tid = threadIdx.x;
    int lane = tid & 31, warp = tid >> 5;
    int wrow = (warp & 3) * 16, wcol = (warp >> 2) * 32;
    int grp = lane >> 2, tig = lane & 3, kp = tig * 2;
    int q0 = blockIdx.x * 64;
    int bnt = blockIdx.y;
    int b = bnt >> 2, n0 = (bnt & 3) * 64;

    int arow = tid >> 2, aseg = tid & 3;
    int bk = tid >> 3, bnq = tid & 7;

    float y[4][4] = {};
    float rb[8];
    const int NIT = 8;   // K=256 / 32

    {
        size_t off = (size_t)(q0 + arow) * 256 + aseg * 8;
        cp16(saddr(&AhS[0][arow * AR + aseg * 8]), &g_powh[l][off]);
        cp16(saddr(&AlS[0][arow * AR + aseg * 8]), &g_powl[l][off]);
        cp_commit();
        float4 r0 = *(const float4*)&Bm[(size_t)bk * BN + b * NCH + n0 + bnq * 8];
        float4 r1 = *(const float4*)&Bm[(size_t)bk * BN + b * NCH + n0 + bnq * 8 + 4];
        rb[0]=r0.x; rb[1]=r0.y; rb[2]=r0.z; rb[3]=r0.w;
        rb[4]=r1.x; rb[5]=r1.y; rb[6]=r1.z; rb[7]=r1.w;
    }

    for (int it = 0; it < NIT; it++) {
        int buf = it & 1;
        cp_wait0();
        #pragma unroll
        for (int j = 0; j < 8; j++) {
            unsigned short h, lo;
            split_bf16(rb[j], h, lo);
            int idx = (bnq * 8 + j) * BR + bk;
            BhS[buf][idx] = h;
            BlS[buf][idx] = lo;
        }
        __syncthreads();

        if (it + 1 < NIT) {
            int c = it + 1, kc = c * 32;
            size_t off = (size_t)(q0 + arow) * 256 + kc + aseg * 8;
            cp16(saddr(&AhS[buf ^ 1][arow * AR + aseg * 8]), &g_powh[l][off]);
            cp16(saddr(&AlS[buf ^ 1][arow * AR + aseg * 8]), &g_powl[l][off]);
            cp_commit();
            float4 r0 = *(const float4*)&Bm[(size_t)(kc + bk) * BN + b * NCH + n0 + bnq * 8];
            float4 r1 = *(const float4*)&Bm[(size_t)(kc + bk) * BN + b * NCH + n0 + bnq * 8 + 4];
            rb[0]=r0.x; rb[1]=r0.y; rb[2]=r0.z; rb[3]=r0.w;
            rb[4]=r1.x; rb[5]=r1.y; rb[6]=r1.z; rb[7]=r1.w;
        }

        #pragma unroll
        for (int s = 0; s < 2; s++) {
            int ko = s * 16;
            unsigned ah[4], al[4];
            int r0i = (wrow + grp) * AR + ko + kp;
            int r1i = (wrow + grp + 8) * AR + ko + kp;
            ah[0] = *(const unsigned*)&AhS[buf][r0i];
            ah[1] = *(const unsigned*)&AhS[buf][r1i];
            ah[2] = *(const unsigned*)&AhS[buf][r0i + 8];
            ah[3] = *(const unsigned*)&AhS[buf][r1i + 8];
            al[0] = *(const unsigned*)&AlS[buf][r0i];
            al[1] = *(const unsigned*)&AlS[buf][r1i];
            al[2] = *(const unsigned*)&AlS[buf][r0i + 8];
            al[3] = *(const unsigned*)&AlS[buf][r1i + 8];
            #pragma unroll
            for (int nt = 0; nt < 4; nt++) {
                int ci = (wcol + nt * 8 + grp) * BR + ko + kp;
                unsigned bh0 = *(const unsigned*)&BhS[buf][ci];
                unsigned bh1 = *(const unsigned*)&BhS[buf][ci + 8];
                unsigned bl0 = *(const unsigned*)&BlS[buf][ci];
                unsigned bl1 = *(const unsigned*)&BlS[buf][ci + 8];
                mma16816(y[nt], ah, bh0, bh1);
                mma16816(y[nt], ah, bl0, bl1);
                mma16816(y[nt], al, bh0, bh1);
            }
        }
    }

    // epilogue with de-normalization
    float be = __ldg(&benc[l]);
    int rowq = q0 + wrow + grp;
    float rs0 = g_rowsum[l][rowq];
    float rs1 = g_rowsum[l][rowq + 8];
    #pragma unroll
    for (int nt = 0; nt < 4; nt++) {
        int nn = n0 + wcol + nt * 8 + kp;
        int bn = b * NCH + nn;
        float m0 = g_mean[bn], m1 = g_mean[bn + 1];
        float s0 = g_std[bn],  s1 = g_std[bn + 1];
        float2 o0 = make_float2(y[nt][0] + m0 * (1.f - rs0) + be * s0,
                                y[nt][1] + m1 * (1.f - rs0) + be * s1);
        float2 o1 = make_float2(y[nt][2] + m0 * (1.f - rs1) + be * s0,
                                y[nt][3] + m1 * (1.f - rs1) + be * s1);
        *(float2*)&out[(size_t)b * (LSEG * PER * NCH) + (size_t)(l * PER + rowq) * NCH + nn] = o0;
        *(float2*)&out[(size_t)b * (LSEG * PER * NCH) + (size_t)(l * PER + rowq + 8) * NCH + nn] = o1;
    }
}

// ---------------- l = 0 epilogue (W^0 = I) ----------------
__global__ void k_out_l0(float* __restrict__ out, const float* __restrict__ benc) {
    int g = blockIdx.x * 256 + threadIdx.x;
    int q  = g >> 13;
    int bn = g & 8191;
    int b = bn >> 8, n = bn & 255;
    float be = __ldg(&benc[0]);
    float rs = g_rowsum[0][q];
    float v = g_z[0][q][bn] + g_mean[bn] * (1.f - rs) + be * g_std[bn];
    out[(size_t)b * (LSEG * PER * NCH) + (size_t)q * NCH + n] = v;
}

// ---------------- launcher ----------------
extern "C" void kernel_launch(void* const* d_in, const int* in_sizes, int n_in,
                              void* d_out, int out_size) {
    const float *x = nullptr, *Wb = nullptr, *We = nullptr, *be = nullptr;
    for (int i = 0; i < n_in; i++) {
        if      (in_sizes[i] == BATCH * SEQ * NCH) x  = (const float*)d_in[i];
        else if (in_sizes[i] == PER * PER)         Wb = (const float*)d_in[i];
        else if (in_sizes[i] == LSEG * KSEG)       We = (const float*)d_in[i];
        else if (in_sizes[i] == LSEG)              be = (const float*)d_in[i];
    }
    float* out = (float*)d_out;
    int4 nil = make_int4(0, 0, 0, 0);

    // Launches 1-5 (gemm_z must be #6 for the ncu -s 5 -c 1 window)
    k_pm<<<dim3(4, 8, 2), 256>>>(Wb, make_int4(2, 0, 0, 0), make_int4(1, 0, 0, 1), nil, nil);
    k_pm<<<dim3(4, 8, 2), 256>>>(Wb, make_int4(3, 2, 1, 0), make_int4(4, 2, 2, 0), nil, nil);
    k_pm<<<dim3(4, 8, 4), 256>>>(Wb, make_int4(5, 4, 1, 0), make_int4(6, 4, 2, 0),
                                     make_int4(7, 4, 3, 0), make_int4(8, 4, 4, 0));
    k_powcvt<<<dim3(256, 8), 256>>>();
    k_stats1<<<dim3(32, 8), 256>>>(x);

    // 6: heavy GEMM (tensor, profiled)
    k_gemm_z<<<dim3(4, 128), 256>>>(x, We);

    // remaining dependencies + second GEMM + epilogues
    k_stats2<<<32, 256>>>();
    k_v_rowsums<<<dim3(32, 8), 256>>>();
    k_v_ext    <<<dim3(32, 3), 256>>>();
    k_rowsum<<<4, 256>>>(We);
    k_gemm_out<<<dim3(4, 128, 3), 256>>>(out, be);
    k_out_l0<<<8192, 256>>>(out, be);
}